// round 16
// baseline (speedup 1.0000x reference)
#include <cuda_runtime.h>
#include <cuda_fp16.h>
#include <math.h>
#include <stdint.h>

#define NN 50000
#define NE 600000
#define EPS_V 1e-5f
#define AVG_D_LOG 1.6094379124341003f

// halves
#define H0_ROWS 25088
#define H1_BASE 25088
#define H1_ROWS (NN - H1_BASE)
#define GB0 (H0_ROWS / 128)
#define GB1 ((H1_ROWS + 127) / 128)

typedef unsigned long long u64;

// ---------------- scratch ----------------
__device__ __half g_P[(size_t)NN * 128];
__device__ __half g_Q16[(size_t)NN * 128];
__device__ __half g_h16[(size_t)NN * 128];
__device__ __half g_H3[(size_t)NN * 128];
__device__ __half g_agg[(size_t)NN * 512];
__device__ float g_s1[NN];
__device__ float g_s2[NN];
__device__ int   g_count[NN];
__device__ int   g_offsets[NN + 1];
__device__ int   g_cursor[NN];
__device__ int   g_sorted_src[NE];
__device__ float g_bias1[256];
__device__ __half g_B1T[256 * 128];
__device__ __half g_Wp0T[128 * 128];
__device__ __half g_WmixT[128 * 128];
__device__ __half g_WcatT[384 * 512];
__device__ int   g_blocksums[64];
__device__ int   g_blockoff[64];
__device__ int   g_is64;

// ---------------- helpers ----------------
__global__ void detect_kernel(const void* edst) {
    const int* v = (const int*)edst;
    g_is64 = (v[1] == 0 && v[3] == 0) ? 1 : 0;
}
__device__ __forceinline__ int edge_index(const void* p, int i) {
    if (g_is64) return (int)(((const long long*)p)[i]);
    return ((const int*)p)[i];
}

// ---------------- prep ----------------
__global__ void prep_kernel(const float* __restrict__ W_pre,
                            const float* __restrict__ b_pre,
                            const float* __restrict__ W_post,
                            const float* __restrict__ W_mix) {
    int idx = blockIdx.x * blockDim.x + threadIdx.x;
    if (idx < 256) g_bias1[idx] = (idx < 128) ? 0.f : b_pre[idx - 128];
    if (idx < 256 * 128) {
        int n = idx >> 7, k = idx & 127;
        float v = (n < 128) ? W_pre[k * 128 + n] : W_pre[(128 + k) * 128 + (n - 128)];
        g_B1T[idx] = __float2half_rn(v);
    }
    if (idx < 128 * 128) {
        int n = idx >> 7, k = idx & 127;
        g_Wp0T[idx]  = __float2half_rn(W_post[k * 128 + n]);
        g_WmixT[idx] = __float2half_rn(W_mix[k * 128 + n]);
    }
    if (idx < 384 * 512) {
        int n = idx >> 9, k = idx & 511;
        int grp = n >> 7, jj = n & 127;
        g_WcatT[idx] = __float2half_rn(W_post[(size_t)(128 + grp * 512 + k) * 128 + jj]);
    }
}

__global__ void __launch_bounds__(256) conv_h_kernel(const float* __restrict__ h) {
    int i = blockIdx.x * blockDim.x + threadIdx.x;
    int idx = i * 4;
    if (idx < NN * 128) {
        float4 v = *(const float4*)(h + idx);
        __half2* dst = (__half2*)&g_h16[idx];
        dst[0] = __floats2half2_rn(v.x, v.y);
        dst[1] = __floats2half2_rn(v.z, v.w);
    }
}

// ---------------- sort chain ----------------
__global__ void __launch_bounds__(256) zero_count_kernel() {
    int i = blockIdx.x * blockDim.x + threadIdx.x;
    if (i < NN) g_count[i] = 0;
}
__global__ void hist_kernel(const void* __restrict__ edst) {
    int e = blockIdx.x * blockDim.x + threadIdx.x;
    if (e < NE) atomicAdd(&g_count[edge_index(edst, e)], 1);
}

#define SCAN_BLOCKS ((NN + 1023) / 1024)

__global__ void __launch_bounds__(1024) scanA_kernel() {
    __shared__ int sdata[1024];
    int tid = threadIdx.x;
    int i = blockIdx.x * 1024 + tid;
    int v = (i < NN) ? g_count[i] : 0;
    sdata[tid] = v;
    __syncthreads();
    #pragma unroll
    for (int off = 1; off < 1024; off <<= 1) {
        int t = (tid >= off) ? sdata[tid - off] : 0;
        __syncthreads();
        sdata[tid] += t;
        __syncthreads();
    }
    if (i < NN) g_offsets[i] = sdata[tid] - v;
    if (tid == 1023) g_blocksums[blockIdx.x] = sdata[1023];
}
__global__ void scanB_kernel() {
    if (threadIdx.x == 0) {
        int run = 0;
        for (int b = 0; b < SCAN_BLOCKS; b++) { g_blockoff[b] = run; run += g_blocksums[b]; }
    }
}
__global__ void __launch_bounds__(1024) scanC_kernel() {
    int i = blockIdx.x * 1024 + threadIdx.x;
    if (i < NN) {
        int o = g_offsets[i] + g_blockoff[blockIdx.x];
        g_offsets[i] = o;
        g_cursor[i] = o;
    }
    if (i == 0) g_offsets[NN] = NE;
}
__global__ void scatter_kernel(const void* __restrict__ esrc, const void* __restrict__ edst) {
    int e = blockIdx.x * blockDim.x + threadIdx.x;
    if (e < NE) {
        int d = edge_index(edst, e);
        int s = edge_index(esrc, e);
        g_sorted_src[atomicAdd(&g_cursor[d], 1)] = s;
    }
}

// ---------------- aggregate ----------------
__global__ void __launch_bounds__(128) aggregate_kernel(int nodeBase) {
    int node = nodeBase + blockIdx.x * 2 + (threadIdx.x >> 6);
    if (node >= NN) return;
    int d2 = threadIdx.x & 63;
    int start = g_offsets[node];
    int end = g_offsets[node + 1];
    float2 q = __half22float2(((const __half2*)g_Q16)[(size_t)node * 64 + d2]);
    const __half2* P2 = (const __half2*)g_P;

    float sx[4] = {0.f, 0.f, 0.f, 0.f}, sy[4] = {0.f, 0.f, 0.f, 0.f};
    float qx[4] = {0.f, 0.f, 0.f, 0.f}, qy[4] = {0.f, 0.f, 0.f, 0.f};
    float mxx = -3.4e38f, mxy = -3.4e38f, mnx = 3.4e38f, mny = 3.4e38f;

    int i = start;
    for (; i + 3 < end; i += 4) {
        int srcs[4];
        #pragma unroll
        for (int u = 0; u < 4; u++) srcs[u] = g_sorted_src[i + u];
        float2 p[4];
        #pragma unroll
        for (int u = 0; u < 4; u++) p[u] = __half22float2(P2[(size_t)srcs[u] * 64 + d2]);
        #pragma unroll
        for (int u = 0; u < 4; u++) {
            float vx = fmaxf(p[u].x + q.x, 0.f), vy = fmaxf(p[u].y + q.y, 0.f);
            sx[u] += vx; sy[u] += vy; qx[u] += vx * vx; qy[u] += vy * vy;
            mxx = fmaxf(mxx, vx); mxy = fmaxf(mxy, vy);
            mnx = fminf(mnx, vx); mny = fminf(mny, vy);
        }
    }
    for (; i < end; i++) {
        int s_ = g_sorted_src[i];
        float2 p = __half22float2(P2[(size_t)s_ * 64 + d2]);
        float vx = fmaxf(p.x + q.x, 0.f), vy = fmaxf(p.y + q.y, 0.f);
        sx[0] += vx; sy[0] += vy; qx[0] += vx * vx; qy[0] += vy * vy;
        mxx = fmaxf(mxx, vx); mxy = fmaxf(mxy, vy);
        mnx = fminf(mnx, vx); mny = fminf(mny, vy);
    }
    float sxx = (sx[0] + sx[1]) + (sx[2] + sx[3]);
    float syy = (sy[0] + sy[1]) + (sy[2] + sy[3]);
    float sqx = (qx[0] + qx[1]) + (qx[2] + qx[3]);
    float sqy = (qy[0] + qy[1]) + (qy[2] + qy[3]);

    float degf = (float)(end - start);
    float inv = 1.f / degf;
    float meanx = sxx * inv, meany = syy * inv;
    float varx = fmaxf(sqx * inv - meanx * meanx, 0.f);
    float vary = fmaxf(sqy * inv - meany * meany, 0.f);
    float sdx = sqrtf(varx + EPS_V), sdy = sqrtf(vary + EPS_V);

    __half2* A2 = (__half2*)&g_agg[(size_t)node * 512];
    A2[d2]       = __floats2half2_rn(meanx, meany);
    A2[64 + d2]  = __floats2half2_rn(mxx, mxy);
    A2[128 + d2] = __floats2half2_rn(mnx, mny);
    A2[192 + d2] = __floats2half2_rn(sdx, sdy);
    if (d2 == 0) {
        float ld = logf(degf + 1.f);
        g_s1[node] = ld / AVG_D_LOG;
        g_s2[node] = AVG_D_LOG / ld;
    }
}

// ---------------- shared GEMM building blocks ----------------
#define MMA16816(c, a, b) \
    asm volatile("mma.sync.aligned.m16n8k16.row.col.f32.f16.f16.f32 " \
        "{%0,%1,%2,%3}, {%4,%5,%6,%7}, {%8,%9}, {%0,%1,%2,%3};" \
        : "+f"((c)[0]), "+f"((c)[1]), "+f"((c)[2]), "+f"((c)[3]) \
        : "r"((a)[0]), "r"((a)[1]), "r"((a)[2]), "r"((a)[3]), \
          "r"((b)[0]), "r"((b)[1]))

#define LDSM4(r, a) \
    asm volatile("ldmatrix.sync.aligned.m8n8.x4.shared.b16 {%0,%1,%2,%3}, [%4];" \
        : "=r"((r)[0]), "=r"((r)[1]), "=r"((r)[2]), "=r"((r)[3]) : "r"(a))

#define CPA16(dst, src) asm volatile("cp.async.ca.shared.global [%0], [%1], 16;" :: "r"(dst), "l"(src))
#define CPA_COMMIT()    asm volatile("cp.async.commit_group;" ::: "memory")
#define CPA_WAIT0()     asm volatile("cp.async.wait_group 0;" ::: "memory")

#define G2_S 72
#define ARR_H (128 * G2_S)                    // halfs per operand array
#define ARR_BYTES (ARR_H * 2)
#define STAGE_BYTES (2 * ARR_BYTES)
#define G2_SMEM_BYTES (2 * STAGE_BYTES)       // 73728 (tgemm)

// fused234 smem: pipeline(2 stages) + hp(2 chunks) + wm(2 chunks)
#define F_HP_OFF (2 * 2 * ARR_H)              // halfs offset: 36864
#define F_WM_OFF (F_HP_OFF + 2 * ARR_H)       // 55296
#define F_SMEM_BYTES ((F_WM_OFF + 2 * ARR_H) * 2)  // 147456

// ---------------- fp16 mma.sync GEMM (modes 0, 3) ----------------
__global__ void __launch_bounds__(256) tgemm_kernel(
    const __half* __restrict__ ap, const __half* __restrict__ bp,
    __half* __restrict__ Ch, __half* __restrict__ C2h,
    int M, int N, int K, int mode, int nY, int rowBase,
    const float* __restrict__ bias)
{
    extern __shared__ __half sm[];
    uint32_t smem_base = (uint32_t)__cvta_generic_to_shared(sm);

    int tid = threadIdx.x, lane = tid & 31, wid = tid >> 5;
    int warp_m = wid >> 2;
    int warp_n = wid & 3;
    int bid = blockIdx.x;
    int blockRow = rowBase + (bid / nY) * 128, blockCol = (bid % nY) * 128;

    float acc[4][4][4];
    #pragma unroll
    for (int i = 0; i < 4; i++)
        #pragma unroll
        for (int j = 0; j < 4; j++)
            #pragma unroll
            for (int q = 0; q < 4; q++) acc[i][j][q] = 0.f;

    int ldRow = tid >> 1, ldHalf = tid & 1;
    int aRow = blockRow + ldRow; if (aRow > M - 1) aRow = M - 1;
    const __half* gA = ap + (size_t)aRow * K + ldHalf * 32;
    const __half* gB = bp + (size_t)(blockCol + ldRow) * K + ldHalf * 32;
    uint32_t sRowOff = (uint32_t)(ldRow * G2_S + ldHalf * 32) * 2;

    int lane7 = lane & 7;
    int aRowSel = ((lane >> 3) & 1) * 8;
    int aKSel   = ((lane >> 4) & 1) * 8;
    int bRowSel = ((lane >> 4) & 1) * 8;
    int bKSel   = ((lane >> 3) & 1) * 8;

    int nch = K >> 6;

    {
        uint32_t st0 = smem_base + sRowOff;
        #pragma unroll
        for (int j = 0; j < 4; j++) {
            CPA16(st0 + j * 16, (const char*)(gA + j * 8));
            CPA16(st0 + ARR_BYTES + j * 16, (const char*)(gB + j * 8));
        }
        CPA_COMMIT();
    }

    for (int ch = 0; ch < nch; ch++) {
        CPA_WAIT0();
        __syncthreads();
        if (ch + 1 < nch) {
            uint32_t stN = smem_base + ((ch + 1) & 1) * STAGE_BYTES + sRowOff;
            const __half* pA = gA + (ch + 1) * 64;
            const __half* pB = gB + (ch + 1) * 64;
            #pragma unroll
            for (int j = 0; j < 4; j++) {
                CPA16(stN + j * 16, (const char*)(pA + j * 8));
                CPA16(stN + ARR_BYTES + j * 16, (const char*)(pB + j * 8));
            }
        }
        CPA_COMMIT();

        uint32_t stC = smem_base + (ch & 1) * STAGE_BYTES;
        uint32_t bA = stC;
        uint32_t bB = stC + ARR_BYTES;

        #pragma unroll
        for (int ks = 0; ks < 4; ks++) {
            int k0 = ks * 16;
            uint32_t bh[4][2];
            #pragma unroll
            for (int p = 0; p < 2; p++) {
                uint32_t off = (uint32_t)((warp_n * 32 + p * 16 + bRowSel + lane7) * G2_S + k0 + bKSel) * 2;
                LDSM4(&bh[2 * p][0], bB + off);
            }
            #pragma unroll
            for (int mt = 0; mt < 4; mt++) {
                uint32_t off = (uint32_t)((warp_m * 64 + mt * 16 + aRowSel + lane7) * G2_S + k0 + aKSel) * 2;
                uint32_t ah[4];
                LDSM4(ah, bA + off);
                #pragma unroll
                for (int nt = 0; nt < 4; nt++)
                    MMA16816(acc[mt][nt], ah, bh[nt]);
            }
        }
    }

    int fr = lane >> 2;
    #pragma unroll
    for (int mt = 0; mt < 4; mt++) {
        int row0 = blockRow + warp_m * 64 + mt * 16 + fr;
        #pragma unroll
        for (int half = 0; half < 2; half++) {
            int row = row0 + half * 8;
            if (row >= M) continue;
            #pragma unroll
            for (int nt = 0; nt < 4; nt++) {
                int col = blockCol + warp_n * 32 + nt * 8 + ((lane & 3) * 2);
                float v0 = acc[mt][nt][half * 2];
                float v1 = acc[mt][nt][half * 2 + 1];
                if (bias) { v0 += bias[col]; v1 += bias[col + 1]; }
                if (mode == 0) {
                    *(__half2*)&Ch[(size_t)row * N + col] = __floats2half2_rn(v0, v1);
                } else {
                    if (col < 128) {
                        *(__half2*)&Ch[(size_t)row * 128 + col] = __floats2half2_rn(v0, v1);
                    } else {
                        *(__half2*)&C2h[(size_t)row * 128 + (col - 128)] = __floats2half2_rn(v0, v1);
                    }
                }
            }
        }
    }
}

// ---------------- fused GEMM2 + combine + GEMM4 ----------------
// Phase A (x3 col tiles): combined += s_ct * (agg @ WcatT[ct])
// hp(smem) = relu(combined + H3 + b_post)
// Phase B: out = h + leaky_relu(hp @ WmixT + b_mix)
__global__ void __launch_bounds__(256, 1) fused234_kernel(
    const float* __restrict__ h, float* __restrict__ out,
    const float* __restrict__ b_post, const float* __restrict__ b_mix,
    int rowBase)
{
    extern __shared__ __half sm[];
    uint32_t smem_base = (uint32_t)__cvta_generic_to_shared(sm);

    int tid = threadIdx.x, lane = tid & 31, wid = tid >> 5;
    int warp_m = wid >> 2;
    int warp_n = wid & 3;
    int blockRow = rowBase + blockIdx.x * 128;

    int ldRow = tid >> 1, ldHalf = tid & 1;
    int aRow = blockRow + ldRow; if (aRow > NN - 1) aRow = NN - 1;
    const __half* gA = g_agg + (size_t)aRow * 512 + ldHalf * 32;
    uint32_t sRowOff = (uint32_t)(ldRow * G2_S + ldHalf * 32) * 2;

    int lane7 = lane & 7;
    int aRowSel = ((lane >> 3) & 1) * 8;
    int aKSel   = ((lane >> 4) & 1) * 8;
    int bRowSel = ((lane >> 4) & 1) * 8;
    int bKSel   = ((lane >> 3) & 1) * 8;
    int fr = lane >> 2;

    // per-thread row scale factors (8 rows: mt x half)
    float s1v[4][2], s2v[4][2];
    #pragma unroll
    for (int mt = 0; mt < 4; mt++)
        #pragma unroll
        for (int half = 0; half < 2; half++) {
            int row = blockRow + warp_m * 64 + mt * 16 + fr + half * 8;
            int rc = (row < NN) ? row : NN - 1;
            s1v[mt][half] = g_s1[rc];
            s2v[mt][half] = g_s2[rc];
        }

    float combined[4][4][4];
    #pragma unroll
    for (int i = 0; i < 4; i++)
        #pragma unroll
        for (int j = 0; j < 4; j++)
            #pragma unroll
            for (int q = 0; q < 4; q++) combined[i][j][q] = 0.f;

    // preload WmixT into its smem slot (first commit group)
    {
        int n = tid >> 1, kh = tid & 1;
        #pragma unroll
        for (int ch = 0; ch < 2; ch++) {
            const __half* src = g_WmixT + n * 128 + ch * 64 + kh * 32;
            uint32_t dst = smem_base + (uint32_t)(F_WM_OFF + ch * ARR_H + n * G2_S + kh * 32) * 2;
            #pragma unroll
            for (int j = 0; j < 4; j++)
                CPA16(dst + j * 16, (const char*)(src + j * 8));
        }
    }

    // ---- Phase A: 3 column tiles of Wcat, K=512 each ----
    for (int ct = 0; ct < 3; ct++) {
        const __half* gB = g_WcatT + (size_t)(ct * 128 + ldRow) * 512 + ldHalf * 32;

        float acc[4][4][4];
        #pragma unroll
        for (int i = 0; i < 4; i++)
            #pragma unroll
            for (int j = 0; j < 4; j++)
                #pragma unroll
                for (int q = 0; q < 4; q++) acc[i][j][q] = 0.f;

        {
            uint32_t st0 = smem_base + sRowOff;
            #pragma unroll
            for (int j = 0; j < 4; j++) {
                CPA16(st0 + j * 16, (const char*)(gA + j * 8));
                CPA16(st0 + ARR_BYTES + j * 16, (const char*)(gB + j * 8));
            }
            CPA_COMMIT();
        }

        for (int ch = 0; ch < 8; ch++) {
            CPA_WAIT0();
            __syncthreads();
            if (ch + 1 < 8) {
                uint32_t stN = smem_base + ((ch + 1) & 1) * STAGE_BYTES + sRowOff;
                const __half* pA = gA + (ch + 1) * 64;
                const __half* pB = gB + (ch + 1) * 64;
                #pragma unroll
                for (int j = 0; j < 4; j++) {
                    CPA16(stN + j * 16, (const char*)(pA + j * 8));
                    CPA16(stN + ARR_BYTES + j * 16, (const char*)(pB + j * 8));
                }
            }
            CPA_COMMIT();

            uint32_t stC = smem_base + (ch & 1) * STAGE_BYTES;
            uint32_t bA = stC;
            uint32_t bB = stC + ARR_BYTES;

            #pragma unroll
            for (int ks = 0; ks < 4; ks++) {
                int k0 = ks * 16;
                uint32_t bh[4][2];
                #pragma unroll
                for (int p = 0; p < 2; p++) {
                    uint32_t off = (uint32_t)((warp_n * 32 + p * 16 + bRowSel + lane7) * G2_S + k0 + bKSel) * 2;
                    LDSM4(&bh[2 * p][0], bB + off);
                }
                #pragma unroll
                for (int mt = 0; mt < 4; mt++) {
                    uint32_t off = (uint32_t)((warp_m * 64 + mt * 16 + aRowSel + lane7) * G2_S + k0 + aKSel) * 2;
                    uint32_t ah[4];
                    LDSM4(ah, bA + off);
                    #pragma unroll
                    for (int nt = 0; nt < 4; nt++)
                        MMA16816(acc[mt][nt], ah, bh[nt]);
                }
            }
        }
        __syncthreads();   // stage buffers reused next ct

        // fold into combined
        #pragma unroll
        for (int mt = 0; mt < 4; mt++)
            #pragma unroll
            for (int half = 0; half < 2; half++) {
                float s = (ct == 0) ? 1.f : ((ct == 1) ? s1v[mt][half] : s2v[mt][half]);
                #pragma unroll
                for (int nt = 0; nt < 4; nt++) {
                    combined[mt][nt][half * 2]     += s * acc[mt][nt][half * 2];
                    combined[mt][nt][half * 2 + 1] += s * acc[mt][nt][half * 2 + 1];
                }
            }
    }

    // ---- combine -> hp(smem) ----
    #pragma unroll
    for (int mt = 0; mt < 4; mt++) {
        #pragma unroll
        for (int half = 0; half < 2; half++) {
            int rl = warp_m * 64 + mt * 16 + fr + half * 8;
            int row = blockRow + rl;
            int rc = (row < NN) ? row : NN - 1;
            #pragma unroll
            for (int nt = 0; nt < 4; nt++) {
                int col = warp_n * 32 + nt * 8 + ((lane & 3) * 2);
                float2 a = __half22float2(*(const __half2*)&g_H3[(size_t)rc * 128 + col]);
                float v0 = combined[mt][nt][half * 2]     + a.x + b_post[col];
                float v1 = combined[mt][nt][half * 2 + 1] + a.y + b_post[col + 1];
                v0 = fmaxf(v0, 0.f);
                v1 = fmaxf(v1, 0.f);
                int chnk = col >> 6, cc = col & 63;
                *(__half2*)&sm[F_HP_OFF + chnk * ARR_H + rl * G2_S + cc] = __floats2half2_rn(v0, v1);
            }
        }
    }
    CPA_WAIT0();          // WmixT surely resident
    __syncthreads();

    // ---- Phase B: hp @ WmixT, K=128 ----
    float acc[4][4][4];
    #pragma unroll
    for (int i = 0; i < 4; i++)
        #pragma unroll
        for (int j = 0; j < 4; j++)
            #pragma unroll
            for (int q = 0; q < 4; q++) acc[i][j][q] = 0.f;

    #pragma unroll
    for (int ch = 0; ch < 2; ch++) {
        uint32_t bA = smem_base + (uint32_t)(F_HP_OFF + ch * ARR_H) * 2;
        uint32_t bB = smem_base + (uint32_t)(F_WM_OFF + ch * ARR_H) * 2;
        #pragma unroll
        for (int ks = 0; ks < 4; ks++) {
            int k0 = ks * 16;
            uint32_t bh[4][2];
            #pragma unroll
            for (int p = 0; p < 2; p++) {
                uint32_t off = (uint32_t)((warp_n * 32 + p * 16 + bRowSel + lane7) * G2_S + k0 + bKSel) * 2;
                LDSM4(&bh[2 * p][0], bB + off);
            }
            #pragma unroll
            for (int mt = 0; mt < 4; mt++) {
                uint32_t off = (uint32_t)((warp_m * 64 + mt * 16 + aRowSel + lane7) * G2_S + k0 + aKSel) * 2;
                uint32_t ah[4];
                LDSM4(ah, bA + off);
                #pragma unroll
                for (int nt = 0; nt < 4; nt++)
                    MMA16816(acc[mt][nt], ah, bh[nt]);
            }
        }
    }

    // epilogue: out = h + leaky_relu(acc + b_mix)
    #pragma unroll
    for (int mt = 0; mt < 4; mt++) {
        int row0 = blockRow + warp_m * 64 + mt * 16 + fr;
        #pragma unroll
        for (int half = 0; half < 2; half++) {
            int row = row0 + half * 8;
            if (row >= NN) continue;
            #pragma unroll
            for (int nt = 0; nt < 4; nt++) {
                int col = warp_n * 32 + nt * 8 + ((lane & 3) * 2);
                float v0 = acc[mt][nt][half * 2] + b_mix[col];
                float v1 = acc[mt][nt][half * 2 + 1] + b_mix[col + 1];
                v0 = (v0 > 0.f) ? v0 : 0.01f * v0;
                v1 = (v1 > 0.f) ? v1 : 0.01f * v1;
                size_t o = (size_t)row * 128 + col;
                v0 += h[o];
                v1 += h[o + 1];
                *(float2*)&out[o] = make_float2(v0, v1);
            }
        }
    }
}

// ---------------- launch ----------------
extern "C" void kernel_launch(void* const* d_in, const int* in_sizes, int n_in,
                              void* d_out, int out_size) {
    const float* h      = (const float*)d_in[0];
    const void*  esrc   = d_in[1];
    const void*  edst   = d_in[2];
    const float* W_pre  = (const float*)d_in[3];
    const float* b_pre  = (const float*)d_in[4];
    const float* W_post = (const float*)d_in[5];
    const float* b_post = (const float*)d_in[6];
    const float* W_mix  = (const float*)d_in[7];
    const float* b_mix  = (const float*)d_in[8];
    float* out = (float*)d_out;

    float *bias1;
    __half *P, *Q16, *h16, *H3;
    __half *B1T, *Wp0T;
    cudaGetSymbolAddress((void**)&P, g_P);
    cudaGetSymbolAddress((void**)&Q16, g_Q16);
    cudaGetSymbolAddress((void**)&h16, g_h16);
    cudaGetSymbolAddress((void**)&H3, g_H3);
    cudaGetSymbolAddress((void**)&bias1, g_bias1);
    cudaGetSymbolAddress((void**)&B1T, g_B1T);
    cudaGetSymbolAddress((void**)&Wp0T, g_Wp0T);

    static int init_done = 0;
    static cudaStream_t s_side;
    static cudaEvent_t ev_fork, ev_prep, ev_pq, ev_h3, ev_sorted, ev_side_done;
    if (!init_done) {
        cudaFuncSetAttribute(tgemm_kernel, cudaFuncAttributeMaxDynamicSharedMemorySize, G2_SMEM_BYTES);
        cudaFuncSetAttribute(fused234_kernel, cudaFuncAttributeMaxDynamicSharedMemorySize, F_SMEM_BYTES);
        cudaStreamCreateWithFlags(&s_side, cudaStreamNonBlocking);
        cudaEventCreateWithFlags(&ev_fork, cudaEventDisableTiming);
        cudaEventCreateWithFlags(&ev_prep, cudaEventDisableTiming);
        cudaEventCreateWithFlags(&ev_pq, cudaEventDisableTiming);
        cudaEventCreateWithFlags(&ev_h3, cudaEventDisableTiming);
        cudaEventCreateWithFlags(&ev_sorted, cudaEventDisableTiming);
        cudaEventCreateWithFlags(&ev_side_done, cudaEventDisableTiming);
        init_done = 1;
    }

    // ---- main: prologue ----
    detect_kernel<<<1, 1>>>(edst);

    // ---- fork side: sort chain ----
    cudaEventRecord(ev_fork, 0);
    cudaStreamWaitEvent(s_side, ev_fork, 0);
    zero_count_kernel<<<(NN + 255) / 256, 256, 0, s_side>>>();
    hist_kernel<<<(NE + 255) / 256, 256, 0, s_side>>>(edst);
    scanA_kernel<<<SCAN_BLOCKS, 1024, 0, s_side>>>();
    scanB_kernel<<<1, 32, 0, s_side>>>();
    scanC_kernel<<<SCAN_BLOCKS, 1024, 0, s_side>>>();
    scatter_kernel<<<(NE + 255) / 256, 256, 0, s_side>>>(esrc, edst);
    cudaEventRecord(ev_sorted, s_side);

    // ---- main: prep + conv ----
    prep_kernel<<<768, 256>>>(W_pre, b_pre, W_post, W_mix);
    conv_h_kernel<<<(NN * 128 / 4 + 255) / 256, 256>>>(h);
    cudaEventRecord(ev_prep, 0);

    // ---- side: H3 = h16 @ Wp0T ----
    cudaStreamWaitEvent(s_side, ev_prep, 0);
    tgemm_kernel<<<(NN + 127) / 128, 256, G2_SMEM_BYTES, s_side>>>(
        h16, Wp0T, H3, nullptr, NN, 128, 128, 0, 1, 0, nullptr);
    cudaEventRecord(ev_h3, s_side);

    // ---- main: GEMM1 (mode 3) ----
    tgemm_kernel<<<((NN + 127) / 128) * 2, 256, G2_SMEM_BYTES>>>(
        h16, B1T, P, Q16, NN, 256, 128, 3, 2, 0, bias1);
    cudaEventRecord(ev_pq, 0);

    // ---- side: aggregate(H1) + fused(H1) (needs P/Q [ev_pq]; CSR, H3, s1/s2 in-stream) ----
    cudaStreamWaitEvent(s_side, ev_pq, 0);
    aggregate_kernel<<<(H1_ROWS + 1) / 2, 128, 0, s_side>>>(H1_BASE);
    fused234_kernel<<<GB1, 256, F_SMEM_BYTES, s_side>>>(h, out, b_post, b_mix, H1_BASE);
    cudaEventRecord(ev_side_done, s_side);

    // ---- main: aggregate(H0) + fused(H0) (needs CSR [ev_sorted], H3 [ev_h3]) ----
    cudaStreamWaitEvent(0, ev_sorted, 0);
    aggregate_kernel<<<H0_ROWS / 2, 128>>>(0);
    cudaStreamWaitEvent(0, ev_h3, 0);
    fused234_kernel<<<GB0, 256, F_SMEM_BYTES>>>(h, out, b_post, b_mix, 0);

    // ---- join ----
    cudaStreamWaitEvent(0, ev_side_done, 0);
}

// round 17
// speedup vs baseline: 1.0647x; 1.0647x over previous
#include <cuda_runtime.h>
#include <cuda_fp16.h>
#include <math.h>
#include <stdint.h>

#define NN 50000
#define NE 600000
#define EPS_V 1e-5f
#define AVG_D_LOG 1.6094379124341003f

#define H0_ROWS 25088
#define H1_BASE 25088
#define H1_ROWS (NN - H1_BASE)
#define GB0 (H0_ROWS / 128)
#define GB1 ((H1_ROWS + 127) / 128)

typedef unsigned long long u64;

// ---------------- scratch ----------------
__device__ __half g_P[(size_t)NN * 128];
__device__ __half g_Q16[(size_t)NN * 128];
__device__ __half g_h16[(size_t)NN * 128];
__device__ __half g_H3[(size_t)NN * 128];
__device__ __half g_agg[(size_t)NN * 512];
__device__ __half g_hp[(size_t)NN * 128];
__device__ __half g_G[(size_t)NN * 384];
__device__ float g_s1[NN];
__device__ float g_s2[NN];
__device__ int   g_count[NN];
__device__ int   g_offsets[NN + 1];
__device__ int   g_cursor[NN];
__device__ int   g_sorted_src[NE];
__device__ float g_bias1[256];
__device__ __half g_B1T[256 * 128];
__device__ __half g_Wp0T[128 * 128];
__device__ __half g_WmixT[128 * 128];
__device__ __half g_WcatT[384 * 512];
__device__ int   g_blocksums[64];
__device__ int   g_blockoff[64];
__device__ int   g_is64;

// ---------------- helpers ----------------
__global__ void detect_kernel(const void* edst) {
    const int* v = (const int*)edst;
    g_is64 = (v[1] == 0 && v[3] == 0) ? 1 : 0;
}
__device__ __forceinline__ int edge_index(const void* p, int i) {
    if (g_is64) return (int)(((const long long*)p)[i]);
    return ((const int*)p)[i];
}

// ---------------- prep ----------------
__global__ void prep_kernel(const float* __restrict__ W_pre,
                            const float* __restrict__ b_pre,
                            const float* __restrict__ W_post,
                            const float* __restrict__ W_mix) {
    int idx = blockIdx.x * blockDim.x + threadIdx.x;
    if (idx < 256) g_bias1[idx] = (idx < 128) ? 0.f : b_pre[idx - 128];
    if (idx < 256 * 128) {
        int n = idx >> 7, k = idx & 127;
        float v = (n < 128) ? W_pre[k * 128 + n] : W_pre[(128 + k) * 128 + (n - 128)];
        g_B1T[idx] = __float2half_rn(v);
    }
    if (idx < 128 * 128) {
        int n = idx >> 7, k = idx & 127;
        g_Wp0T[idx]  = __float2half_rn(W_post[k * 128 + n]);
        g_WmixT[idx] = __float2half_rn(W_mix[k * 128 + n]);
    }
    if (idx < 384 * 512) {
        int n = idx >> 9, k = idx & 511;
        int grp = n >> 7, jj = n & 127;
        g_WcatT[idx] = __float2half_rn(W_post[(size_t)(128 + grp * 512 + k) * 128 + jj]);
    }
}

__global__ void __launch_bounds__(256) conv_h_kernel(const float* __restrict__ h) {
    int i = blockIdx.x * blockDim.x + threadIdx.x;
    int idx = i * 4;
    if (idx < NN * 128) {
        float4 v = *(const float4*)(h + idx);
        __half2* dst = (__half2*)&g_h16[idx];
        dst[0] = __floats2half2_rn(v.x, v.y);
        dst[1] = __floats2half2_rn(v.z, v.w);
    }
}

// ---------------- sort chain ----------------
__global__ void __launch_bounds__(256) zero_count_kernel() {
    int i = blockIdx.x * blockDim.x + threadIdx.x;
    if (i < NN) g_count[i] = 0;
}
__global__ void hist_kernel(const void* __restrict__ edst) {
    int e = blockIdx.x * blockDim.x + threadIdx.x;
    if (e < NE) atomicAdd(&g_count[edge_index(edst, e)], 1);
}

#define SCAN_BLOCKS ((NN + 1023) / 1024)

__global__ void __launch_bounds__(1024) scanA_kernel() {
    __shared__ int sdata[1024];
    int tid = threadIdx.x;
    int i = blockIdx.x * 1024 + tid;
    int v = (i < NN) ? g_count[i] : 0;
    sdata[tid] = v;
    __syncthreads();
    #pragma unroll
    for (int off = 1; off < 1024; off <<= 1) {
        int t = (tid >= off) ? sdata[tid - off] : 0;
        __syncthreads();
        sdata[tid] += t;
        __syncthreads();
    }
    if (i < NN) g_offsets[i] = sdata[tid] - v;
    if (tid == 1023) g_blocksums[blockIdx.x] = sdata[1023];
}
__global__ void scanB_kernel() {
    if (threadIdx.x == 0) {
        int run = 0;
        for (int b = 0; b < SCAN_BLOCKS; b++) { g_blockoff[b] = run; run += g_blocksums[b]; }
    }
}
__global__ void __launch_bounds__(1024) scanC_kernel() {
    int i = blockIdx.x * 1024 + threadIdx.x;
    if (i < NN) {
        int o = g_offsets[i] + g_blockoff[blockIdx.x];
        g_offsets[i] = o;
        g_cursor[i] = o;
    }
    if (i == 0) g_offsets[NN] = NE;
}
__global__ void scatter_kernel(const void* __restrict__ esrc, const void* __restrict__ edst) {
    int e = blockIdx.x * blockDim.x + threadIdx.x;
    if (e < NE) {
        int d = edge_index(edst, e);
        int s = edge_index(esrc, e);
        g_sorted_src[atomicAdd(&g_cursor[d], 1)] = s;
    }
}

// ---------------- aggregate ----------------
__global__ void __launch_bounds__(128) aggregate_kernel(int nodeBase) {
    int node = nodeBase + blockIdx.x * 2 + (threadIdx.x >> 6);
    if (node >= NN) return;
    int d2 = threadIdx.x & 63;
    int start = g_offsets[node];
    int end = g_offsets[node + 1];
    float2 q = __half22float2(((const __half2*)g_Q16)[(size_t)node * 64 + d2]);
    const __half2* P2 = (const __half2*)g_P;

    float sx[4] = {0.f, 0.f, 0.f, 0.f}, sy[4] = {0.f, 0.f, 0.f, 0.f};
    float qx[4] = {0.f, 0.f, 0.f, 0.f}, qy[4] = {0.f, 0.f, 0.f, 0.f};
    float mxx = -3.4e38f, mxy = -3.4e38f, mnx = 3.4e38f, mny = 3.4e38f;

    int i = start;
    for (; i + 3 < end; i += 4) {
        int srcs[4];
        #pragma unroll
        for (int u = 0; u < 4; u++) srcs[u] = g_sorted_src[i + u];
        float2 p[4];
        #pragma unroll
        for (int u = 0; u < 4; u++) p[u] = __half22float2(P2[(size_t)srcs[u] * 64 + d2]);
        #pragma unroll
        for (int u = 0; u < 4; u++) {
            float vx = fmaxf(p[u].x + q.x, 0.f), vy = fmaxf(p[u].y + q.y, 0.f);
            sx[u] += vx; sy[u] += vy; qx[u] += vx * vx; qy[u] += vy * vy;
            mxx = fmaxf(mxx, vx); mxy = fmaxf(mxy, vy);
            mnx = fminf(mnx, vx); mny = fminf(mny, vy);
        }
    }
    for (; i < end; i++) {
        int s_ = g_sorted_src[i];
        float2 p = __half22float2(P2[(size_t)s_ * 64 + d2]);
        float vx = fmaxf(p.x + q.x, 0.f), vy = fmaxf(p.y + q.y, 0.f);
        sx[0] += vx; sy[0] += vy; qx[0] += vx * vx; qy[0] += vy * vy;
        mxx = fmaxf(mxx, vx); mxy = fmaxf(mxy, vy);
        mnx = fminf(mnx, vx); mny = fminf(mny, vy);
    }
    float sxx = (sx[0] + sx[1]) + (sx[2] + sx[3]);
    float syy = (sy[0] + sy[1]) + (sy[2] + sy[3]);
    float sqx = (qx[0] + qx[1]) + (qx[2] + qx[3]);
    float sqy = (qy[0] + qy[1]) + (qy[2] + qy[3]);

    float degf = (float)(end - start);
    float inv = 1.f / degf;
    float meanx = sxx * inv, meany = syy * inv;
    float varx = fmaxf(sqx * inv - meanx * meanx, 0.f);
    float vary = fmaxf(sqy * inv - meany * meany, 0.f);
    float sdx = sqrtf(varx + EPS_V), sdy = sqrtf(vary + EPS_V);

    __half2* A2 = (__half2*)&g_agg[(size_t)node * 512];
    A2[d2]       = __floats2half2_rn(meanx, meany);
    A2[64 + d2]  = __floats2half2_rn(mxx, mxy);
    A2[128 + d2] = __floats2half2_rn(mnx, mny);
    A2[192 + d2] = __floats2half2_rn(sdx, sdy);
    if (d2 == 0) {
        float ld = logf(degf + 1.f);
        g_s1[node] = ld / AVG_D_LOG;
        g_s2[node] = AVG_D_LOG / ld;
    }
}

// ---------------- combine ----------------
__global__ void __launch_bounds__(256) combine_kernel(const float* __restrict__ b_post,
                                                      int rowBase, int nRows) {
    int idx = blockIdx.x * blockDim.x + threadIdx.x;
    if (idx >= nRows * 64) return;
    int i = rowBase * 64 + idx;
    int row = i >> 6;
    int c2 = i & 63;
    float s1v = g_s1[row], s2v = g_s2[row];
    float2 a = __half22float2(((const __half2*)g_H3)[i]);
    const __half2* Gr = (const __half2*)(g_G + (size_t)row * 384);
    float2 g0 = __half22float2(Gr[c2]);
    float2 g1 = __half22float2(Gr[64 + c2]);
    float2 g2 = __half22float2(Gr[128 + c2]);
    float2 b = *(const float2*)&b_post[c2 * 2];
    float v0 = a.x + b.x + g0.x + s1v * g1.x + s2v * g2.x;
    float v1 = a.y + b.y + g0.y + s1v * g1.y + s2v * g2.y;
    v0 = fmaxf(v0, 0.f);
    v1 = fmaxf(v1, 0.f);
    ((__half2*)g_hp)[i] = __floats2half2_rn(v0, v1);
}

// ---------------- shared GEMM building blocks ----------------
#define MMA16816(c, a, b) \
    asm volatile("mma.sync.aligned.m16n8k16.row.col.f32.f16.f16.f32 " \
        "{%0,%1,%2,%3}, {%4,%5,%6,%7}, {%8,%9}, {%0,%1,%2,%3};" \
        : "+f"((c)[0]), "+f"((c)[1]), "+f"((c)[2]), "+f"((c)[3]) \
        : "r"((a)[0]), "r"((a)[1]), "r"((a)[2]), "r"((a)[3]), \
          "r"((b)[0]), "r"((b)[1]))

#define LDSM4(r, a) \
    asm volatile("ldmatrix.sync.aligned.m8n8.x4.shared.b16 {%0,%1,%2,%3}, [%4];" \
        : "=r"((r)[0]), "=r"((r)[1]), "=r"((r)[2]), "=r"((r)[3]) : "r"(a))

#define CPA16(dst, src) asm volatile("cp.async.ca.shared.global [%0], [%1], 16;" :: "r"(dst), "l"(src))
#define CPA_COMMIT()    asm volatile("cp.async.commit_group;" ::: "memory")
#define CPA_WAIT0()     asm volatile("cp.async.wait_group 0;" ::: "memory")

#define G2_S 72
#define ARR_BYTES (128 * G2_S * 2)
#define STAGE_BYTES (2 * ARR_BYTES)
#define G2_SMEM_BYTES (2 * STAGE_BYTES)

// ---------------- fp16 mma.sync GEMM (modes 0, 2, 3) ----------------
__global__ void __launch_bounds__(256) tgemm_kernel(
    const __half* __restrict__ ap, const __half* __restrict__ bp,
    float* __restrict__ C, __half* __restrict__ Ch, __half* __restrict__ C2h,
    int M, int N, int K, int mode, int nY, int rowBase,
    const float* __restrict__ bias, const float* __restrict__ resid)
{
    extern __shared__ __half sm[];
    uint32_t smem_base = (uint32_t)__cvta_generic_to_shared(sm);

    int tid = threadIdx.x, lane = tid & 31, wid = tid >> 5;
    int warp_m = wid >> 2;
    int warp_n = wid & 3;
    int bid = blockIdx.x;
    int blockRow = rowBase + (bid / nY) * 128, blockCol = (bid % nY) * 128;

    float acc[4][4][4];
    #pragma unroll
    for (int i = 0; i < 4; i++)
        #pragma unroll
        for (int j = 0; j < 4; j++)
            #pragma unroll
            for (int q = 0; q < 4; q++) acc[i][j][q] = 0.f;

    int ldRow = tid >> 1, ldHalf = tid & 1;
    int aRow = blockRow + ldRow; if (aRow > M - 1) aRow = M - 1;
    const __half* gA = ap + (size_t)aRow * K + ldHalf * 32;
    const __half* gB = bp + (size_t)(blockCol + ldRow) * K + ldHalf * 32;
    uint32_t sRowOff = (uint32_t)(ldRow * G2_S + ldHalf * 32) * 2;

    int lane7 = lane & 7;
    int aRowSel = ((lane >> 3) & 1) * 8;
    int aKSel   = ((lane >> 4) & 1) * 8;
    int bRowSel = ((lane >> 4) & 1) * 8;
    int bKSel   = ((lane >> 3) & 1) * 8;

    int nch = K >> 6;

    {
        uint32_t st0 = smem_base + sRowOff;
        #pragma unroll
        for (int j = 0; j < 4; j++) {
            CPA16(st0 + j * 16, (const char*)(gA + j * 8));
            CPA16(st0 + ARR_BYTES + j * 16, (const char*)(gB + j * 8));
        }
        CPA_COMMIT();
    }

    for (int ch = 0; ch < nch; ch++) {
        CPA_WAIT0();
        __syncthreads();
        if (ch + 1 < nch) {
            uint32_t stN = smem_base + ((ch + 1) & 1) * STAGE_BYTES + sRowOff;
            const __half* pA = gA + (ch + 1) * 64;
            const __half* pB = gB + (ch + 1) * 64;
            #pragma unroll
            for (int j = 0; j < 4; j++) {
                CPA16(stN + j * 16, (const char*)(pA + j * 8));
                CPA16(stN + ARR_BYTES + j * 16, (const char*)(pB + j * 8));
            }
        }
        CPA_COMMIT();

        uint32_t stC = smem_base + (ch & 1) * STAGE_BYTES;
        uint32_t bA = stC;
        uint32_t bB = stC + ARR_BYTES;

        #pragma unroll
        for (int ks = 0; ks < 4; ks++) {
            int k0 = ks * 16;
            uint32_t bh[4][2];
            #pragma unroll
            for (int p = 0; p < 2; p++) {
                uint32_t off = (uint32_t)((warp_n * 32 + p * 16 + bRowSel + lane7) * G2_S + k0 + bKSel) * 2;
                LDSM4(&bh[2 * p][0], bB + off);
            }
            #pragma unroll
            for (int mt = 0; mt < 4; mt++) {
                uint32_t off = (uint32_t)((warp_m * 64 + mt * 16 + aRowSel + lane7) * G2_S + k0 + aKSel) * 2;
                uint32_t ah[4];
                LDSM4(ah, bA + off);
                #pragma unroll
                for (int nt = 0; nt < 4; nt++)
                    MMA16816(acc[mt][nt], ah, bh[nt]);
            }
        }
    }

    int fr = lane >> 2;
    #pragma unroll
    for (int mt = 0; mt < 4; mt++) {
        int row0 = blockRow + warp_m * 64 + mt * 16 + fr;
        #pragma unroll
        for (int half = 0; half < 2; half++) {
            int row = row0 + half * 8;
            if (row >= M) continue;
            #pragma unroll
            for (int nt = 0; nt < 4; nt++) {
                int col = blockCol + warp_n * 32 + nt * 8 + ((lane & 3) * 2);
                float v0 = acc[mt][nt][half * 2];
                float v1 = acc[mt][nt][half * 2 + 1];
                if (bias) { v0 += bias[col]; v1 += bias[col + 1]; }
                if (mode == 0) {
                    if (Ch) *(__half2*)&Ch[(size_t)row * N + col] = __floats2half2_rn(v0, v1);
                    else    *(float2*)&C[(size_t)row * N + col] = make_float2(v0, v1);
                } else if (mode == 2) {
                    v0 = (v0 > 0.f) ? v0 : 0.01f * v0;
                    v1 = (v1 > 0.f) ? v1 : 0.01f * v1;
                    size_t o = (size_t)row * 128 + col;
                    v0 += resid[o];
                    v1 += resid[o + 1];
                    *(float2*)&C[o] = make_float2(v0, v1);
                } else {
                    if (col < 128) {
                        *(__half2*)&Ch[(size_t)row * 128 + col] = __floats2half2_rn(v0, v1);
                    } else {
                        *(__half2*)&C2h[(size_t)row * 128 + (col - 128)] = __floats2half2_rn(v0, v1);
                    }
                }
            }
        }
    }
}

// ---------------- launch ----------------
extern "C" void kernel_launch(void* const* d_in, const int* in_sizes, int n_in,
                              void* d_out, int out_size) {
    const float* h      = (const float*)d_in[0];
    const void*  esrc   = d_in[1];
    const void*  edst   = d_in[2];
    const float* W_pre  = (const float*)d_in[3];
    const float* b_pre  = (const float*)d_in[4];
    const float* W_post = (const float*)d_in[5];
    const float* b_post = (const float*)d_in[6];
    const float* W_mix  = (const float*)d_in[7];
    const float* b_mix  = (const float*)d_in[8];
    float* out = (float*)d_out;

    float *bias1;
    __half *P, *Q16, *h16, *H3, *agg, *hp, *G;
    __half *B1T, *Wp0T, *WmixT, *WcatT;
    cudaGetSymbolAddress((void**)&P, g_P);
    cudaGetSymbolAddress((void**)&Q16, g_Q16);
    cudaGetSymbolAddress((void**)&h16, g_h16);
    cudaGetSymbolAddress((void**)&H3, g_H3);
    cudaGetSymbolAddress((void**)&agg, g_agg);
    cudaGetSymbolAddress((void**)&hp, g_hp);
    cudaGetSymbolAddress((void**)&G, g_G);
    cudaGetSymbolAddress((void**)&bias1, g_bias1);
    cudaGetSymbolAddress((void**)&B1T, g_B1T);
    cudaGetSymbolAddress((void**)&Wp0T, g_Wp0T);
    cudaGetSymbolAddress((void**)&WmixT, g_WmixT);
    cudaGetSymbolAddress((void**)&WcatT, g_WcatT);

    static int init_done = 0;
    static cudaStream_t s_side;
    static cudaEvent_t ev_fork, ev_prep, ev_pq, ev_h3, ev_sorted, ev_side_done;
    if (!init_done) {
        cudaFuncSetAttribute(tgemm_kernel, cudaFuncAttributeMaxDynamicSharedMemorySize, G2_SMEM_BYTES);
        cudaStreamCreateWithFlags(&s_side, cudaStreamNonBlocking);
        cudaEventCreateWithFlags(&ev_fork, cudaEventDisableTiming);
        cudaEventCreateWithFlags(&ev_prep, cudaEventDisableTiming);
        cudaEventCreateWithFlags(&ev_pq, cudaEventDisableTiming);
        cudaEventCreateWithFlags(&ev_h3, cudaEventDisableTiming);
        cudaEventCreateWithFlags(&ev_sorted, cudaEventDisableTiming);
        cudaEventCreateWithFlags(&ev_side_done, cudaEventDisableTiming);
        init_done = 1;
    }

    // ---- main: prologue ----
    detect_kernel<<<1, 1>>>(edst);

    // ---- fork side: sort chain ----
    cudaEventRecord(ev_fork, 0);
    cudaStreamWaitEvent(s_side, ev_fork, 0);
    zero_count_kernel<<<(NN + 255) / 256, 256, 0, s_side>>>();
    hist_kernel<<<(NE + 255) / 256, 256, 0, s_side>>>(edst);
    scanA_kernel<<<SCAN_BLOCKS, 1024, 0, s_side>>>();
    scanB_kernel<<<1, 32, 0, s_side>>>();
    scanC_kernel<<<SCAN_BLOCKS, 1024, 0, s_side>>>();
    scatter_kernel<<<(NE + 255) / 256, 256, 0, s_side>>>(esrc, edst);
    cudaEventRecord(ev_sorted, s_side);

    // ---- main: prep + conv ----
    prep_kernel<<<768, 256>>>(W_pre, b_pre, W_post, W_mix);
    conv_h_kernel<<<(NN * 128 / 4 + 255) / 256, 256>>>(h);
    cudaEventRecord(ev_prep, 0);

    // ---- side: H3 = h16 @ Wp0T ----
    cudaStreamWaitEvent(s_side, ev_prep, 0);
    tgemm_kernel<<<(NN + 127) / 128, 256, G2_SMEM_BYTES, s_side>>>(
        h16, Wp0T, nullptr, H3, nullptr, NN, 128, 128, 0, 1, 0, nullptr, nullptr);
    cudaEventRecord(ev_h3, s_side);

    // ---- main: GEMM1 full (mode 3) ----
    tgemm_kernel<<<((NN + 127) / 128) * 2, 256, G2_SMEM_BYTES>>>(
        h16, B1T, nullptr, P, Q16, NN, 256, 128, 3, 2, 0, bias1, nullptr);
    cudaEventRecord(ev_pq, 0);

    // ---- side chain (H1): agg -> GEMM2 -> combine -> GEMM4 (in-stream after CSR+H3) ----
    cudaStreamWaitEvent(s_side, ev_pq, 0);
    aggregate_kernel<<<(H1_ROWS + 1) / 2, 128, 0, s_side>>>(H1_BASE);
    tgemm_kernel<<<GB1 * 3, 256, G2_SMEM_BYTES, s_side>>>(
        agg, WcatT, nullptr, G, nullptr, NN, 384, 512, 0, 3, H1_BASE, nullptr, nullptr);
    combine_kernel<<<(H1_ROWS * 64 + 255) / 256, 256, 0, s_side>>>(b_post, H1_BASE, H1_ROWS);
    tgemm_kernel<<<GB1, 256, G2_SMEM_BYTES, s_side>>>(
        hp, WmixT, out, nullptr, nullptr, NN, 128, 128, 2, 1, H1_BASE, b_mix, h);
    cudaEventRecord(ev_side_done, s_side);

    // ---- main chain (H0): agg (needs CSR) -> GEMM2 -> combine (needs H3) -> GEMM4 ----
    cudaStreamWaitEvent(0, ev_sorted, 0);
    aggregate_kernel<<<H0_ROWS / 2, 128>>>(0);
    tgemm_kernel<<<GB0 * 3, 256, G2_SMEM_BYTES>>>(
        agg, WcatT, nullptr, G, nullptr, NN, 384, 512, 0, 3, 0, nullptr, nullptr);
    cudaStreamWaitEvent(0, ev_h3, 0);
    combine_kernel<<<(H0_ROWS * 64 + 255) / 256, 256>>>(b_post, 0, H0_ROWS);
    tgemm_kernel<<<GB0, 256, G2_SMEM_BYTES>>>(
        hp, WmixT, out, nullptr, nullptr, NN, 128, 128, 2, 1, 0, b_mix, h);

    // ---- join ----
    cudaStreamWaitEvent(0, ev_side_done, 0);
}